// round 14
// baseline (speedup 1.0000x reference)
#include <cuda_runtime.h>

// Problem shapes (fixed by setup_inputs)
#define BB 64
#define TT 1024
#define JJ 32
#define TOTAL (BB * TT * JJ)

// Scratch: per-(b,t) root trajectory, float4-padded. 4 MB.
__device__ float4 d_traj[BB * TT];

// Rotate point p by unit quaternion q=(w,x,y,z): p' = p + w*t + u×t, t = 2*(u×p)
__device__ __forceinline__ void qrotate(float w, float x, float y, float z,
                                        float px, float py, float pz,
                                        float& ox, float& oy, float& oz) {
    float tx = 2.0f * (y * pz - z * py);
    float ty = 2.0f * (z * px - x * pz);
    float tz = 2.0f * (x * py - y * px);
    ox = px + w * tx + (y * tz - z * ty);
    oy = py + w * ty + (z * tx - x * tz);
    oz = pz + w * tz + (x * ty - y * tx);
}

// Kernel 1: blocks [0,64) = per-batch trajectory scan (dispatched first, so
// they start immediately); blocks [64, 64+8192) = rot path (independent of
// traj, streams glb_rot -> rot_out and hides the scan's wall time).
// No inter-block communication of any kind.
__global__ void __launch_bounds__(256)
scan_plus_rot_kernel(const float* __restrict__ glb_pos,
                     const float* __restrict__ glb_rot,
                     const float* __restrict__ glb_vel,
                     const float* __restrict__ root,
                     float* __restrict__ out) {
    const int bid = blockIdx.x;
    const int tid = threadIdx.x;

    if (bid < BB) {
        // ---------- per-batch trajectory scan (verified in R13) ----------
        const int b = bid;
        __shared__ float wsx[8], wsy[8], wsz[8];
        const int lane = tid & 31, warp = tid >> 5;

        // e[t] = rot(inv[t-1], vel[t-1, joint0]), e[0] = 0; 4 t-steps per thread
        float ex[4], ey[4], ez[4];
        #pragma unroll
        for (int k = 0; k < 4; k++) {
            int t = tid * 4 + k;
            ex[k] = ey[k] = ez[k] = 0.0f;
            if (t >= 1) {
                int s = t - 1;
                float4 q = __ldg((const float4*)(root + (size_t)(b * TT + s) * 4));
                float4 v = __ldg((const float4*)(glb_vel +
                                 (size_t)(b * (TT - 1) + s) * JJ * 3));  // joint0 (+pad)
                qrotate(q.x, -q.y, -q.z, -q.w, v.x, v.y, v.z, ex[k], ey[k], ez[k]);
            }
        }
        #pragma unroll
        for (int k = 1; k < 4; k++) { ex[k] += ex[k-1]; ey[k] += ey[k-1]; ez[k] += ez[k-1]; }
        const float thx = ex[3], thy = ey[3], thz = ez[3];

        float sx = thx, sy = thy, sz = thz;
        #pragma unroll
        for (int d = 1; d < 32; d <<= 1) {
            float nx = __shfl_up_sync(0xffffffffu, sx, d);
            float ny = __shfl_up_sync(0xffffffffu, sy, d);
            float nz = __shfl_up_sync(0xffffffffu, sz, d);
            if (lane >= d) { sx += nx; sy += ny; sz += nz; }
        }
        if (lane == 31) { wsx[warp] = sx; wsy[warp] = sy; wsz[warp] = sz; }
        __syncthreads();
        if (tid == 0) {
            float ax = 0, ay = 0, az = 0;
            #pragma unroll
            for (int w2 = 0; w2 < 8; w2++) {
                float tx = wsx[w2], ty = wsy[w2], tz = wsz[w2];
                wsx[w2] = ax; wsy[w2] = ay; wsz[w2] = az;
                ax += tx; ay += ty; az += tz;
            }
        }
        __syncthreads();

        // base = rot(inv[b,0], pos[b,0,joint0])
        float4 q0 = __ldg((const float4*)(root + (size_t)b * TT * 4));
        float4 p0 = __ldg((const float4*)(glb_pos + (size_t)b * TT * JJ * 3));
        float bx, by, bz;
        qrotate(q0.x, -q0.y, -q0.z, -q0.w, p0.x, p0.y, p0.z, bx, by, bz);

        const float offx = bx + wsx[warp] + (sx - thx);
        const float offy = by + wsy[warp] + (sy - thy);
        const float offz = bz + wsz[warp] + (sz - thz);
        #pragma unroll
        for (int k = 0; k < 4; k++) {
            d_traj[b * TT + tid * 4 + k] =
                make_float4(offx + ex[k], offy + ey[k], offz + ez[k], 0.0f);
        }
        return;
    }

    // ---------- rot path: standardize(inv ⊗ glb_rot), 1 elem/thread ----------
    const int idx  = (bid - BB) * 256 + tid;   // 0 .. TOTAL-1
    const int pair = idx >> 5;                 // (b*T + t), warp-uniform

    const float4 q = __ldg((const float4*)(root + (size_t)pair * 4));
    const float w = q.x, x = -q.y, y = -q.z, z = -q.w;

    const float4 g = __ldg((const float4*)(glb_rot + (size_t)idx * 4));
    float rw = w * g.x - x * g.y - y * g.z - z * g.w;
    float rx = w * g.y + x * g.x + y * g.w - z * g.z;
    float ry = w * g.z - x * g.w + y * g.x + z * g.y;
    float rz = w * g.w + x * g.z - y * g.y + z * g.x;
    float s = (rw < 0.0f) ? -1.0f : 1.0f;
    ((float4*)(out + (size_t)TOTAL * 3))[idx] =
        make_float4(s * rw, s * rx, s * ry, s * rz);
}

// Kernel 2: pos path only — rotate glb_pos by inv(root), add x/z trajectory.
// d_traj written by kernel 1 (previous launch on same stream => visible).
__global__ void __launch_bounds__(256)
pos_kernel(const float* __restrict__ glb_pos,
           const float* __restrict__ root,
           float* __restrict__ out) {
    const int idx = blockIdx.x * blockDim.x + threadIdx.x;  // 0 .. TOTAL-1
    const int pair = idx >> 5;

    const float4 q = __ldg((const float4*)(root + (size_t)pair * 4));
    const float w = q.x, x = -q.y, y = -q.z, z = -q.w;

    const float* p = glb_pos + (size_t)idx * 3;
    float px, py, pz;
    qrotate(w, x, y, z, __ldg(p), __ldg(p + 1), __ldg(p + 2), px, py, pz);

    const float4 tr = __ldg(&d_traj[pair]);   // immutable within this kernel

    float* op = out + (size_t)idx * 3;
    op[0] = px + tr.x;
    op[1] = py;
    op[2] = pz + tr.z;
}

extern "C" void kernel_launch(void* const* d_in, const int* in_sizes, int n_in,
                              void* d_out, int out_size) {
    const float* glb_pos = (const float*)d_in[0];
    const float* glb_rot = (const float*)d_in[1];
    const float* glb_vel = (const float*)d_in[2];
    const float* root    = (const float*)d_in[3];
    float* out = (float*)d_out;

    scan_plus_rot_kernel<<<BB + TOTAL / 256, 256>>>(glb_pos, glb_rot, glb_vel, root, out);
    pos_kernel<<<TOTAL / 256, 256>>>(glb_pos, root, out);
}

// round 15
// speedup vs baseline: 1.0716x; 1.0716x over previous
#include <cuda_runtime.h>

// Problem shapes (fixed by setup_inputs)
#define BB 64
#define TT 1024
#define JJ 32
#define TOTAL (BB * TT * JJ)

// Scratch: per-(b,t) root trajectory, float4-padded. 4 MB.
__device__ float4 d_traj[BB * TT];

// Rotate point p by unit quaternion q=(w,x,y,z): p' = p + w*t + u×t, t = 2*(u×p)
__device__ __forceinline__ void qrotate(float w, float x, float y, float z,
                                        float px, float py, float pz,
                                        float& ox, float& oy, float& oz) {
    float tx = 2.0f * (y * pz - z * py);
    float ty = 2.0f * (z * px - x * pz);
    float tz = 2.0f * (x * py - y * px);
    ox = px + w * tx + (y * tz - z * ty);
    oy = py + w * ty + (z * tx - x * tz);
    oz = pz + w * tz + (x * ty - y * tx);
}

// Kernel 1: per-batch trajectory scan. 64 blocks x 512 threads, 2 t-steps per
// thread: serial local prefix + shfl warp scan + 16-entry smem combine.
__global__ void __launch_bounds__(512)
traj_scan_kernel(const float* __restrict__ glb_pos,
                 const float* __restrict__ glb_vel,
                 const float* __restrict__ root) {
    const int b = blockIdx.x;
    const int tid = threadIdx.x;          // 0..511
    __shared__ float wsx[16], wsy[16], wsz[16];
    const int lane = tid & 31, warp = tid >> 5;

    // e[t] = rot(inv[t-1], vel[t-1, joint0]), e[0] = 0; 2 t-steps per thread
    float ex[2], ey[2], ez[2];
    #pragma unroll
    for (int k = 0; k < 2; k++) {
        int t = tid * 2 + k;
        ex[k] = ey[k] = ez[k] = 0.0f;
        if (t >= 1) {
            int s = t - 1;
            float4 q = __ldg((const float4*)(root + (size_t)(b * TT + s) * 4));
            float4 v = __ldg((const float4*)(glb_vel +
                             (size_t)(b * (TT - 1) + s) * JJ * 3));  // joint0 (+pad)
            qrotate(q.x, -q.y, -q.z, -q.w, v.x, v.y, v.z, ex[k], ey[k], ez[k]);
        }
    }
    ex[1] += ex[0]; ey[1] += ey[0]; ez[1] += ez[0];
    const float thx = ex[1], thy = ey[1], thz = ez[1];

    // warp-inclusive scan of per-thread sums
    float sx = thx, sy = thy, sz = thz;
    #pragma unroll
    for (int d = 1; d < 32; d <<= 1) {
        float nx = __shfl_up_sync(0xffffffffu, sx, d);
        float ny = __shfl_up_sync(0xffffffffu, sy, d);
        float nz = __shfl_up_sync(0xffffffffu, sz, d);
        if (lane >= d) { sx += nx; sy += ny; sz += nz; }
    }
    if (lane == 31) { wsx[warp] = sx; wsy[warp] = sy; wsz[warp] = sz; }
    __syncthreads();
    if (tid == 0) {
        float ax = 0, ay = 0, az = 0;
        #pragma unroll
        for (int w2 = 0; w2 < 16; w2++) {
            float tx = wsx[w2], ty = wsy[w2], tz = wsz[w2];
            wsx[w2] = ax; wsy[w2] = ay; wsz[w2] = az;
            ax += tx; ay += ty; az += tz;
        }
    }
    __syncthreads();

    // base = rot(inv[b,0], pos[b,0,joint0])
    float4 q0 = __ldg((const float4*)(root + (size_t)b * TT * 4));
    float4 p0 = __ldg((const float4*)(glb_pos + (size_t)b * TT * JJ * 3));
    float bx, by, bz;
    qrotate(q0.x, -q0.y, -q0.z, -q0.w, p0.x, p0.y, p0.z, bx, by, bz);

    const float offx = bx + wsx[warp] + (sx - thx);
    const float offy = by + wsy[warp] + (sy - thy);
    const float offz = bz + wsz[warp] + (sz - thz);
    #pragma unroll
    for (int k = 0; k < 2; k++) {
        d_traj[b * TT + tid * 2 + k] =
            make_float4(offx + ex[k], offy + ey[k], offz + ez[k], 0.0f);
    }
}

// Kernel 2: elementwise main work. 2 elements per thread, WARP-STRIDED
// (idx and idx+256) so every global access stays fully coalesced while
// doubling per-thread MLP. Outputs via streaming stores (__stcs) so the
// 56 MB written-once output doesn't evict the input set from L2.
__global__ void __launch_bounds__(256)
main_kernel(const float* __restrict__ glb_pos,
            const float* __restrict__ glb_rot,
            const float* __restrict__ root,
            float* __restrict__ out) {
    const int tid = threadIdx.x;
    const int idx0 = blockIdx.x * 512 + tid;   // elements [bid*512, bid*512+512)
    const int idx1 = idx0 + 256;

    // ---- issue all independent loads up front ----
    const float4 qA = __ldg((const float4*)(root + (size_t)(idx0 >> 5) * 4));
    const float4 qB = __ldg((const float4*)(root + (size_t)(idx1 >> 5) * 4));
    const float4 gA = __ldg((const float4*)(glb_rot + (size_t)idx0 * 4));
    const float4 gB = __ldg((const float4*)(glb_rot + (size_t)idx1 * 4));
    const float* pA = glb_pos + (size_t)idx0 * 3;
    const float* pB = glb_pos + (size_t)idx1 * 3;
    const float pax = __ldg(pA), pay = __ldg(pA + 1), paz = __ldg(pA + 2);
    const float pbx = __ldg(pB), pby = __ldg(pB + 1), pbz = __ldg(pB + 2);
    const float4 trA = __ldg(&d_traj[idx0 >> 5]);
    const float4 trB = __ldg(&d_traj[idx1 >> 5]);

    float4* rotOut = (float4*)(out + (size_t)TOTAL * 3);

    // ---- element A ----
    {
        const float w = qA.x, x = -qA.y, y = -qA.z, z = -qA.w;
        float rw = w * gA.x - x * gA.y - y * gA.z - z * gA.w;
        float rx = w * gA.y + x * gA.x + y * gA.w - z * gA.z;
        float ry = w * gA.z - x * gA.w + y * gA.x + z * gA.y;
        float rz = w * gA.w + x * gA.z - y * gA.y + z * gA.x;
        float s = (rw < 0.0f) ? -1.0f : 1.0f;
        __stcs(&rotOut[idx0], make_float4(s * rw, s * rx, s * ry, s * rz));

        float ox, oy, oz;
        qrotate(w, x, y, z, pax, pay, paz, ox, oy, oz);
        float* op = out + (size_t)idx0 * 3;
        __stcs(op,     ox + trA.x);
        __stcs(op + 1, oy);
        __stcs(op + 2, oz + trA.z);
    }

    // ---- element B ----
    {
        const float w = qB.x, x = -qB.y, y = -qB.z, z = -qB.w;
        float rw = w * gB.x - x * gB.y - y * gB.z - z * gB.w;
        float rx = w * gB.y + x * gB.x + y * gB.w - z * gB.z;
        float ry = w * gB.z - x * gB.w + y * gB.x + z * gB.y;
        float rz = w * gB.w + x * gB.z - y * gB.y + z * gB.x;
        float s = (rw < 0.0f) ? -1.0f : 1.0f;
        __stcs(&rotOut[idx1], make_float4(s * rw, s * rx, s * ry, s * rz));

        float ox, oy, oz;
        qrotate(w, x, y, z, pbx, pby, pbz, ox, oy, oz);
        float* op = out + (size_t)idx1 * 3;
        __stcs(op,     ox + trB.x);
        __stcs(op + 1, oy);
        __stcs(op + 2, oz + trB.z);
    }
}

extern "C" void kernel_launch(void* const* d_in, const int* in_sizes, int n_in,
                              void* d_out, int out_size) {
    const float* glb_pos = (const float*)d_in[0];
    const float* glb_rot = (const float*)d_in[1];
    const float* glb_vel = (const float*)d_in[2];
    const float* root    = (const float*)d_in[3];
    float* out = (float*)d_out;

    traj_scan_kernel<<<BB, 512>>>(glb_pos, glb_vel, root);
    main_kernel<<<TOTAL / 512, 256>>>(glb_pos, glb_rot, root, out);
}